// round 2
// baseline (speedup 1.0000x reference)
#include <cuda_runtime.h>

#define NB 4
#define NS 2048
#define ND 1024
#define NH 16
#define NDH 64

static constexpr float ATT_SCALE = 0.125f;  // 64^-0.5

// Scratch (allocation-free): head-major Q/K/V [B,H,S,DH] and attention output [B,S,H*DH]
__device__ float g_q[NB * NH * NS * NDH];
__device__ float g_k[NB * NH * NS * NDH];
__device__ float g_v[NB * NH * NS * NDH];
__device__ float g_ao[NB * NS * ND];

// ---------------------------------------------------------------------------
// GEMM: C = A[M,K] @ W[K,N], M=8192, K=N=1024.
// 128x128 block tile, KT=16, 256 threads, 8x8 per thread.
// MODE 0: plain row-major C[m*N+n]
// MODE 1: permuted write to [B,H,S,DH] (for Q/K/V head-major scratch)
// ---------------------------------------------------------------------------
template <int MODE>
__global__ __launch_bounds__(256)
void gemm_k(const float* __restrict__ A, const float* __restrict__ W,
            float* __restrict__ C) {
    const int Kd = ND, N = ND;
    __shared__ float As[16][132];  // transposed A tile, padded vs bank conflicts
    __shared__ float Bs[16][128];

    const int tid = threadIdx.x;
    const int tx = tid & 15, ty = tid >> 4;
    const int m0 = blockIdx.y << 7, n0 = blockIdx.x << 7;

    float acc[8][8];
#pragma unroll
    for (int i = 0; i < 8; i++)
#pragma unroll
        for (int j = 0; j < 8; j++) acc[i][j] = 0.f;

    const int a_row = tid >> 2, a_c = (tid & 3) << 2;   // 64 rows/pass, 4 floats
    const int b_row = tid >> 5, b_c = (tid & 31) << 2;  // 8 rows/pass, 4 floats

    for (int k0 = 0; k0 < Kd; k0 += 16) {
#pragma unroll
        for (int p = 0; p < 2; p++) {
            float4 v = *(const float4*)(A + (size_t)(m0 + a_row + 64 * p) * Kd + k0 + a_c);
            As[a_c + 0][a_row + 64 * p] = v.x;
            As[a_c + 1][a_row + 64 * p] = v.y;
            As[a_c + 2][a_row + 64 * p] = v.z;
            As[a_c + 3][a_row + 64 * p] = v.w;
        }
#pragma unroll
        for (int p = 0; p < 2; p++) {
            *(float4*)&Bs[b_row + 8 * p][b_c] =
                *(const float4*)(W + (size_t)(k0 + b_row + 8 * p) * N + n0 + b_c);
        }
        __syncthreads();

#pragma unroll
        for (int kk = 0; kk < 16; kk++) {
            float a[8], b[8];
            *(float4*)&a[0] = *(const float4*)&As[kk][ty * 8];
            *(float4*)&a[4] = *(const float4*)&As[kk][ty * 8 + 4];
            *(float4*)&b[0] = *(const float4*)&Bs[kk][tx * 8];
            *(float4*)&b[4] = *(const float4*)&Bs[kk][tx * 8 + 4];
#pragma unroll
            for (int i = 0; i < 8; i++)
#pragma unroll
                for (int j = 0; j < 8; j++)
                    acc[i][j] = fmaf(a[i], b[j], acc[i][j]);
        }
        __syncthreads();
    }

    if (MODE == 0) {
#pragma unroll
        for (int i = 0; i < 8; i++) {
            int m = m0 + ty * 8 + i;
            float* dst = C + (size_t)m * N + n0 + tx * 8;
            *(float4*)(dst)     = make_float4(acc[i][0], acc[i][1], acc[i][2], acc[i][3]);
            *(float4*)(dst + 4) = make_float4(acc[i][4], acc[i][5], acc[i][6], acc[i][7]);
        }
    } else {
#pragma unroll
        for (int i = 0; i < 8; i++) {
            int m = m0 + ty * 8 + i;
            int b_ = m >> 11, s = m & (NS - 1);       // m = b*S + s
            int n = n0 + tx * 8;
            int h = n >> 6, d = n & 63;               // n = h*64 + d (8 elems stay in-head)
            float* dst = C + ((size_t)(b_ * NH + h) * NS + s) * NDH + d;
            *(float4*)(dst)     = make_float4(acc[i][0], acc[i][1], acc[i][2], acc[i][3]);
            *(float4*)(dst + 4) = make_float4(acc[i][4], acc[i][5], acc[i][6], acc[i][7]);
        }
    }
}

// ---------------------------------------------------------------------------
// Flash attention, fp32, causal. BLOCK_M = BLOCK_N = 64, 256 threads (16x16,
// each thread 4x4). Causal tiles beyond the diagonal are skipped entirely.
// Grid: (S/64, B*H)
// ---------------------------------------------------------------------------
__global__ __launch_bounds__(256)
void flash_k() {
    extern __shared__ float smembuf[];
    float* Qs = smembuf;             // [64][64]
    float* Ks = Qs + 64 * 64;        // [64][65] padded (2-way instead of 16-way)
    float* Vs = Ks + 64 * 65;        // [64][64]
    float* Ps = Vs + 64 * 64;        // [64][64]

    const int tid = threadIdx.x;
    const int tx = tid & 15, ty = tid >> 4;
    const int qt = blockIdx.x, bh = blockIdx.y;
    const int q0 = qt << 6;

    const float* Qb = g_q + (size_t)bh * NS * NDH;
    const float* Kb = g_k + (size_t)bh * NS * NDH;
    const float* Vb = g_v + (size_t)bh * NS * NDH;

    // Load Q tile (visibility covered by the first __syncthreads below)
    for (int t = tid; t < 1024; t += 256) {
        int r = t >> 4, c = (t & 15) << 2;
        *(float4*)&Qs[r * 64 + c] = *(const float4*)&Qb[(size_t)(q0 + r) * NDH + c];
    }

    float acc[4][4];
    float mrow[4], lrow[4];
#pragma unroll
    for (int i = 0; i < 4; i++) {
        mrow[i] = -1e30f;
        lrow[i] = 0.f;
#pragma unroll
        for (int j = 0; j < 4; j++) acc[i][j] = 0.f;
    }

    for (int j0 = 0; j0 <= q0; j0 += 64) {
        // Load K (scalar stores into padded rows) and V tiles
        for (int t = tid; t < 1024; t += 256) {
            int r = t >> 4, c = (t & 15) << 2;
            float4 kv = *(const float4*)&Kb[(size_t)(j0 + r) * NDH + c];
            float* kp = &Ks[r * 65 + c];
            kp[0] = kv.x; kp[1] = kv.y; kp[2] = kv.z; kp[3] = kv.w;
            *(float4*)&Vs[r * 64 + c] = *(const float4*)&Vb[(size_t)(j0 + r) * NDH + c];
        }
        __syncthreads();

        // S = Q @ K^T
        float s[4][4];
#pragma unroll
        for (int i = 0; i < 4; i++)
#pragma unroll
            for (int j = 0; j < 4; j++) s[i][j] = 0.f;

#pragma unroll 4
        for (int d = 0; d < 64; d++) {
            float qa[4], kb[4];
#pragma unroll
            for (int i = 0; i < 4; i++) qa[i] = Qs[(ty * 4 + i) * 64 + d];
#pragma unroll
            for (int j = 0; j < 4; j++) kb[j] = Ks[(tx * 4 + j) * 65 + d];
#pragma unroll
            for (int i = 0; i < 4; i++)
#pragma unroll
                for (int j = 0; j < 4; j++)
                    s[i][j] = fmaf(qa[i], kb[j], s[i][j]);
        }

        const bool diag = (j0 == q0);

        // Online softmax (row stats reduced over the 16 tx-lanes of each row)
#pragma unroll
        for (int i = 0; i < 4; i++) {
            float mloc = -1e30f;
#pragma unroll
            for (int j = 0; j < 4; j++) {
                float val = s[i][j] * ATT_SCALE;
                if (diag && (j0 + tx * 4 + j) > (q0 + ty * 4 + i)) val = -1e30f;
                s[i][j] = val;
                mloc = fmaxf(mloc, val);
            }
#pragma unroll
            for (int off = 8; off; off >>= 1)
                mloc = fmaxf(mloc, __shfl_xor_sync(0xffffffffu, mloc, off));

            float mnew = fmaxf(mrow[i], mloc);
            float alpha = __expf(mrow[i] - mnew);
            mrow[i] = mnew;

            float lsum = 0.f;
#pragma unroll
            for (int j = 0; j < 4; j++) {
                float p = __expf(s[i][j] - mnew);
                s[i][j] = p;
                lsum += p;
            }
#pragma unroll
            for (int off = 8; off; off >>= 1)
                lsum += __shfl_xor_sync(0xffffffffu, lsum, off);

            lrow[i] = lrow[i] * alpha + lsum;
#pragma unroll
            for (int j = 0; j < 4; j++) acc[i][j] *= alpha;

            *(float4*)&Ps[(ty * 4 + i) * 64 + tx * 4] =
                make_float4(s[i][0], s[i][1], s[i][2], s[i][3]);
        }
        __syncthreads();

        // O += P @ V
#pragma unroll 4
        for (int c = 0; c < 64; c++) {
            float4 v4 = *(const float4*)&Vs[c * 64 + tx * 4];
#pragma unroll
            for (int i = 0; i < 4; i++) {
                float p = Ps[(ty * 4 + i) * 64 + c];
                acc[i][0] = fmaf(p, v4.x, acc[i][0]);
                acc[i][1] = fmaf(p, v4.y, acc[i][1]);
                acc[i][2] = fmaf(p, v4.z, acc[i][2]);
                acc[i][3] = fmaf(p, v4.w, acc[i][3]);
            }
        }
        __syncthreads();  // protect tile buffers for next iteration
    }

    // Write normalized output into [B, S, H*DH] layout
    const int b_ = bh >> 4, h = bh & 15;
#pragma unroll
    for (int i = 0; i < 4; i++) {
        int srow = q0 + ty * 4 + i;
        float inv = 1.0f / lrow[i];
        float* dst = g_ao + ((size_t)(b_ * NS + srow)) * ND + h * NDH + tx * 4;
        *(float4*)dst = make_float4(acc[i][0] * inv, acc[i][1] * inv,
                                    acc[i][2] * inv, acc[i][3] * inv);
    }
}

// ---------------------------------------------------------------------------
// Launch
// ---------------------------------------------------------------------------
extern "C" void kernel_launch(void* const* d_in, const int* in_sizes, int n_in,
                              void* d_out, int out_size) {
    const float* x_q = (const float*)d_in[0];
    const float* x_k = (const float*)d_in[1];
    const float* x_v = (const float*)d_in[2];
    // d_in[3] = mask (bool): deterministic causal triu(k=1) — applied analytically.
    const float* Wq = (const float*)d_in[4];
    const float* Wk = (const float*)d_in[5];
    const float* Wv = (const float*)d_in[6];
    const float* Wo = (const float*)d_in[7];
    float* out = (float*)d_out;

    float *q, *k, *v, *ao;
    cudaGetSymbolAddress((void**)&q, g_q);
    cudaGetSymbolAddress((void**)&k, g_k);
    cudaGetSymbolAddress((void**)&v, g_v);
    cudaGetSymbolAddress((void**)&ao, g_ao);

    dim3 ggrid(ND / 128, (NB * NS) / 128);  // (8, 64)

    gemm_k<1><<<ggrid, 256>>>(x_q, Wq, q);
    gemm_k<1><<<ggrid, 256>>>(x_k, Wk, k);
    gemm_k<1><<<ggrid, 256>>>(x_v, Wv, v);

    size_t smem = (size_t)(64 * 64 + 64 * 65 + 64 * 64 + 64 * 64) * sizeof(float);
    cudaFuncSetAttribute(flash_k, cudaFuncAttributeMaxDynamicSharedMemorySize, (int)smem);
    flash_k<<<dim3(NS / 64, NB * NH), 256, smem>>>();

    gemm_k<0><<<ggrid, 256>>>(ao, Wo, out);
}

// round 4
// speedup vs baseline: 1.0303x; 1.0303x over previous
#include <cuda_runtime.h>

#define NB 4
#define NS 2048
#define ND 1024
#define NH 16
#define NDH 64

static constexpr float ATT_SCALE = 0.125f;  // 64^-0.5

typedef unsigned long long ull;

// Scratch (allocation-free): head-major Q/K/V [B,H,S,DH] and attention output [B,S,H*DH]
__device__ float g_q[NB * NH * NS * NDH];
__device__ float g_k[NB * NH * NS * NDH];
__device__ float g_v[NB * NH * NS * NDH];
__device__ float g_ao[NB * NS * ND];

// ---------------------------------------------------------------------------
// Packed f32x2 helpers (Blackwell dual-FP32 path; ptxas never emits these
// from C++ — PTX only).
// ---------------------------------------------------------------------------
__device__ __forceinline__ ull pack2(float x, float y) {
    ull r;
    asm("mov.b64 %0, {%1, %2};" : "=l"(r) : "f"(x), "f"(y));
    return r;
}
__device__ __forceinline__ ull pack2(float x) {
    ull r;
    asm("mov.b64 %0, {%1, %1};" : "=l"(r) : "f"(x));
    return r;
}
__device__ __forceinline__ void ffma2(ull& d, ull a, ull b) {
    asm("fma.rn.f32x2 %0, %1, %2, %0;" : "+l"(d) : "l"(a), "l"(b));
}
__device__ __forceinline__ ull mul2(ull a, ull b) {
    ull r;
    asm("mul.rn.f32x2 %0, %1, %2;" : "=l"(r) : "l"(a), "l"(b));
    return r;
}
__device__ __forceinline__ float2 unpack2(ull v) {
    float2 f;
    asm("mov.b64 {%0, %1}, %2;" : "=f"(f.x), "=f"(f.y) : "l"(v));
    return f;
}

// ---------------------------------------------------------------------------
// GEMM: C = A[M,K] @ W[K,N], M=8192, K=N=1024.
// 128x128 block tile, KT=16, 256 threads, 8x8 per thread, f32x2 accumulators.
// MODE 0: plain row-major C[m*N+n]
// MODE 1: permuted write to [B,H,S,DH] (for Q/K/V head-major scratch)
// ---------------------------------------------------------------------------
template <int MODE>
__global__ __launch_bounds__(256)
void gemm_k(const float* __restrict__ A, const float* __restrict__ W,
            float* __restrict__ C) {
    const int Kd = ND, N = ND;
    __shared__ float As[16][132];  // transposed A tile, padded vs bank conflicts
    __shared__ float Bs[16][128];

    const int tid = threadIdx.x;
    const int tx = tid & 15, ty = tid >> 4;
    const int m0 = blockIdx.y << 7, n0 = blockIdx.x << 7;

    // acc2[i][j2]: lanes are columns (tx*8 + 2*j2, tx*8 + 2*j2 + 1)
    ull acc2[8][4];
#pragma unroll
    for (int i = 0; i < 8; i++)
#pragma unroll
        for (int j = 0; j < 4; j++) acc2[i][j] = 0ull;

    const int a_row = tid >> 2, a_c = (tid & 3) << 2;   // 64 rows/pass, 4 floats
    const int b_row = tid >> 5, b_c = (tid & 31) << 2;  // 8 rows/pass, 4 floats

    for (int k0 = 0; k0 < Kd; k0 += 16) {
#pragma unroll
        for (int p = 0; p < 2; p++) {
            float4 v = *(const float4*)(A + (size_t)(m0 + a_row + 64 * p) * Kd + k0 + a_c);
            As[a_c + 0][a_row + 64 * p] = v.x;
            As[a_c + 1][a_row + 64 * p] = v.y;
            As[a_c + 2][a_row + 64 * p] = v.z;
            As[a_c + 3][a_row + 64 * p] = v.w;
        }
#pragma unroll
        for (int p = 0; p < 2; p++) {
            *(float4*)&Bs[b_row + 8 * p][b_c] =
                *(const float4*)(W + (size_t)(k0 + b_row + 8 * p) * N + n0 + b_c);
        }
        __syncthreads();

#pragma unroll
        for (int kk = 0; kk < 16; kk++) {
            float a[8];
            *(float4*)&a[0] = *(const float4*)&As[kk][ty * 8];
            *(float4*)&a[4] = *(const float4*)&As[kk][ty * 8 + 4];
            float4 bv0 = *(const float4*)&Bs[kk][tx * 8];
            float4 bv1 = *(const float4*)&Bs[kk][tx * 8 + 4];
            ull b2[4];
            b2[0] = pack2(bv0.x, bv0.y);
            b2[1] = pack2(bv0.z, bv0.w);
            b2[2] = pack2(bv1.x, bv1.y);
            b2[3] = pack2(bv1.z, bv1.w);
#pragma unroll
            for (int i = 0; i < 8; i++) {
                ull ai = pack2(a[i]);
#pragma unroll
                for (int j = 0; j < 4; j++) ffma2(acc2[i][j], ai, b2[j]);
            }
        }
        __syncthreads();
    }

#pragma unroll
    for (int i = 0; i < 8; i++) {
        float2 u0 = unpack2(acc2[i][0]);
        float2 u1 = unpack2(acc2[i][1]);
        float2 u2 = unpack2(acc2[i][2]);
        float2 u3 = unpack2(acc2[i][3]);
        int m = m0 + ty * 8 + i;
        float* dst;
        if (MODE == 0) {
            dst = C + (size_t)m * N + n0 + tx * 8;
        } else {
            int b_ = m >> 11, s = m & (NS - 1);  // m = b*S + s
            int n = n0 + tx * 8;
            int h = n >> 6, d = n & 63;          // 8 output elems stay within one head
            dst = C + ((size_t)(b_ * NH + h) * NS + s) * NDH + d;
        }
        *(float4*)(dst)     = make_float4(u0.x, u0.y, u1.x, u1.y);
        *(float4*)(dst + 4) = make_float4(u2.x, u2.y, u3.x, u3.y);
    }
}

// ---------------------------------------------------------------------------
// Flash attention, fp32, causal. BLOCK_M = BLOCK_N = 64, 256 threads (16x16,
// each thread 4x4, f32x2 accumulators). K tile stored d-major so both QK
// operand streams are float4 LDS. Causal tiles beyond diagonal skipped.
// Grid: (S/64, B*H)
// ---------------------------------------------------------------------------
__global__ __launch_bounds__(256)
void flash_k() {
    extern __shared__ float smembuf[];
    float* Qs = smembuf;             // [64][64]  row = q, col = d
    float* Kt = Qs + 64 * 64;        // [64][68]  row = d, col = n (padded)
    float* Vs = Kt + 64 * 68;        // [64][64]  row = kpos, col = d
    float* Ps = Vs + 64 * 64;        // [64][64]  row = q, col = kpos

    const int tid = threadIdx.x;
    const int tx = tid & 15, ty = tid >> 4;
    const int qt = blockIdx.x, bh = blockIdx.y;
    const int q0 = qt << 6;

    const float* Qb = g_q + (size_t)bh * NS * NDH;
    const float* Kb = g_k + (size_t)bh * NS * NDH;
    const float* Vb = g_v + (size_t)bh * NS * NDH;

    // Load Q tile (visibility covered by the first __syncthreads below)
    for (int t = tid; t < 1024; t += 256) {
        int r = t >> 4, c = (t & 15) << 2;
        *(float4*)&Qs[r * 64 + c] = *(const float4*)&Qb[(size_t)(q0 + r) * NDH + c];
    }

    // acc2[i][j2]: lanes are output d-cols (tx*4 + 2*j2, +1)
    ull acc2[4][2];
    float mrow[4], lrow[4];
#pragma unroll
    for (int i = 0; i < 4; i++) {
        mrow[i] = -1e30f;
        lrow[i] = 0.f;
        acc2[i][0] = 0ull;
        acc2[i][1] = 0ull;
    }

    for (int j0 = 0; j0 <= q0; j0 += 64) {
        // Load K transposed (scalar stores into d-major padded rows) and V tile
        for (int t = tid; t < 1024; t += 256) {
            int r = t >> 4, c = (t & 15) << 2;  // r = k-position, c = d offset
            float4 kv = *(const float4*)&Kb[(size_t)(j0 + r) * NDH + c];
            Kt[(c + 0) * 68 + r] = kv.x;
            Kt[(c + 1) * 68 + r] = kv.y;
            Kt[(c + 2) * 68 + r] = kv.z;
            Kt[(c + 3) * 68 + r] = kv.w;
            *(float4*)&Vs[r * 64 + c] = *(const float4*)&Vb[(size_t)(j0 + r) * NDH + c];
        }
        __syncthreads();

        // S = Q @ K^T with f32x2: lanes pair adjacent n-columns
        ull s2[4][2];
#pragma unroll
        for (int i = 0; i < 4; i++) { s2[i][0] = 0ull; s2[i][1] = 0ull; }

#pragma unroll 4
        for (int d4 = 0; d4 < 64; d4 += 4) {
            float4 q4[4], k4[4];
#pragma unroll
            for (int i = 0; i < 4; i++)
                q4[i] = *(const float4*)&Qs[(ty * 4 + i) * 64 + d4];
#pragma unroll
            for (int dd = 0; dd < 4; dd++)
                k4[dd] = *(const float4*)&Kt[(d4 + dd) * 68 + tx * 4];
#pragma unroll
            for (int dd = 0; dd < 4; dd++) {
                ull kb0 = pack2(k4[dd].x, k4[dd].y);
                ull kb1 = pack2(k4[dd].z, k4[dd].w);
#pragma unroll
                for (int i = 0; i < 4; i++) {
                    float qv = (dd == 0) ? q4[i].x : (dd == 1) ? q4[i].y
                             : (dd == 2) ? q4[i].z : q4[i].w;
                    ull a2 = pack2(qv);
                    ffma2(s2[i][0], a2, kb0);
                    ffma2(s2[i][1], a2, kb1);
                }
            }
        }

        const bool diag = (j0 == q0);

        // Online softmax (row stats reduced over the 16 tx-lanes of each row)
#pragma unroll
        for (int i = 0; i < 4; i++) {
            float s[4];
            float2 u0 = unpack2(s2[i][0]);
            float2 u1 = unpack2(s2[i][1]);
            s[0] = u0.x; s[1] = u0.y; s[2] = u1.x; s[3] = u1.y;

            float mloc = -1e30f;
#pragma unroll
            for (int j = 0; j < 4; j++) {
                float val = s[j] * ATT_SCALE;
                if (diag && (j0 + tx * 4 + j) > (q0 + ty * 4 + i)) val = -1e30f;
                s[j] = val;
                mloc = fmaxf(mloc, val);
            }
#pragma unroll
            for (int off = 8; off; off >>= 1)
                mloc = fmaxf(mloc, __shfl_xor_sync(0xffffffffu, mloc, off));

            float mnew = fmaxf(mrow[i], mloc);
            float alpha = __expf(mrow[i] - mnew);
            mrow[i] = mnew;

            float lsum = 0.f;
#pragma unroll
            for (int j = 0; j < 4; j++) {
                float p = __expf(s[j] - mnew);
                s[j] = p;
                lsum += p;
            }
#pragma unroll
            for (int off = 8; off; off >>= 1)
                lsum += __shfl_xor_sync(0xffffffffu, lsum, off);

            lrow[i] = lrow[i] * alpha + lsum;
            ull al2 = pack2(alpha);
            acc2[i][0] = mul2(acc2[i][0], al2);
            acc2[i][1] = mul2(acc2[i][1], al2);

            *(float4*)&Ps[(ty * 4 + i) * 64 + tx * 4] = make_float4(s[0], s[1], s[2], s[3]);
        }
        __syncthreads();

        // O += P @ V with f32x2: lanes pair adjacent d-columns
#pragma unroll 4
        for (int c4 = 0; c4 < 64; c4 += 4) {
            float4 v4[4], p4[4];
#pragma unroll
            for (int cc = 0; cc < 4; cc++)
                v4[cc] = *(const float4*)&Vs[(c4 + cc) * 64 + tx * 4];
#pragma unroll
            for (int i = 0; i < 4; i++)
                p4[i] = *(const float4*)&Ps[(ty * 4 + i) * 64 + c4];
#pragma unroll
            for (int cc = 0; cc < 4; cc++) {
                ull vv0 = pack2(v4[cc].x, v4[cc].y);
                ull vv1 = pack2(v4[cc].z, v4[cc].w);
#pragma unroll
                for (int i = 0; i < 4; i++) {
                    float pv = (cc == 0) ? p4[i].x : (cc == 1) ? p4[i].y
                             : (cc == 2) ? p4[i].z : p4[i].w;
                    ull a2 = pack2(pv);
                    ffma2(acc2[i][0], a2, vv0);
                    ffma2(acc2[i][1], a2, vv1);
                }
            }
        }
        __syncthreads();  // protect tile buffers for next iteration
    }

    // Write normalized output into [B, S, H*DH] layout
    const int b_ = bh >> 4, h = bh & 15;
#pragma unroll
    for (int i = 0; i < 4; i++) {
        int srow = q0 + ty * 4 + i;
        float inv = 1.0f / lrow[i];
        float2 u0 = unpack2(acc2[i][0]);
        float2 u1 = unpack2(acc2[i][1]);
        float* dst = g_ao + ((size_t)(b_ * NS + srow)) * ND + h * NDH + tx * 4;
        *(float4*)dst = make_float4(u0.x * inv, u0.y * inv, u1.x * inv, u1.y * inv);
    }
}

// ---------------------------------------------------------------------------
// Launch
// ---------------------------------------------------------------------------
extern "C" void kernel_launch(void* const* d_in, const int* in_sizes, int n_in,
                              void* d_out, int out_size) {
    const float* x_q = (const float*)d_in[0];
    const float* x_k = (const float*)d_in[1];
    const float* x_v = (const float*)d_in[2];
    // d_in[3] = mask (bool): deterministic causal triu(k=1) — applied analytically.
    const float* Wq = (const float*)d_in[4];
    const float* Wk = (const float*)d_in[5];
    const float* Wv = (const float*)d_in[6];
    const float* Wo = (const float*)d_in[7];
    float* out = (float*)d_out;

    float *q, *k, *v, *ao;
    cudaGetSymbolAddress((void**)&q, g_q);
    cudaGetSymbolAddress((void**)&k, g_k);
    cudaGetSymbolAddress((void**)&v, g_v);
    cudaGetSymbolAddress((void**)&ao, g_ao);

    dim3 ggrid(ND / 128, (NB * NS) / 128);  // (8, 64)

    gemm_k<1><<<ggrid, 256>>>(x_q, Wq, q);
    gemm_k<1><<<ggrid, 256>>>(x_k, Wk, k);
    gemm_k<1><<<ggrid, 256>>>(x_v, Wv, v);

    size_t smem = (size_t)(64 * 64 + 64 * 68 + 64 * 64 + 64 * 64) * sizeof(float);
    cudaFuncSetAttribute(flash_k, cudaFuncAttributeMaxDynamicSharedMemorySize, (int)smem);
    flash_k<<<dim3(NS / 64, NB * NH), 256, smem>>>();

    gemm_k<0><<<ggrid, 256>>>(ao, Wo, out);
}